// round 16
// baseline (speedup 1.0000x reference)
#include <cuda_runtime.h>
#include <cuda_bf16.h>
#include <math.h>
#include <stdint.h>

// Problem constants
#define BB 4
#define HH 4
#define LL 2048
#define DD 1024
#define HD 256
#define ROWS (BB*LL)     // 8192
#define BHN  (BB*HH)     // 16

// ---------------- scratch (device globals; no allocations allowed) ----------
__device__ __nv_bfloat16 g_xn_bf [(size_t)ROWS * DD];       // normalized x (bf16)
__device__ __nv_bfloat16 g_wqkv_bf[(size_t)3 * DD * DD];    // qkv_w in bf16
__device__ __nv_bfloat16 g_wout_bf[(size_t)DD * DD];        // out_w in bf16
__device__ __nv_bfloat16 g_qkv_bf[(size_t)ROWS * 3 * DD];   // qkv projection (bf16)
__device__ __nv_bfloat16 g_q  [(size_t)BHN * LL * HD];      // bf16 [BH,L,hd]
__device__ __nv_bfloat16 g_k  [(size_t)BHN * LL * HD];
__device__ __nv_bfloat16 g_v  [(size_t)BHN * LL * HD];
__device__ __nv_bfloat16 g_ao_bf[(size_t)ROWS * DD];        // attention out (bf16)

// =====================  helpers  ============================================
__device__ __forceinline__ uint32_t smem_u32(const void* p) {
    uint32_t a;
    asm("{ .reg .u64 t; cvta.to.shared.u64 t, %1; cvt.u32.u64 %0, t; }"
        : "=r"(a) : "l"(p));
    return a;
}
__device__ __forceinline__ void ldmx4(uint32_t addr, uint32_t& r0, uint32_t& r1,
                                      uint32_t& r2, uint32_t& r3) {
    asm volatile("ldmatrix.sync.aligned.m8n8.x4.shared.b16 {%0,%1,%2,%3}, [%4];"
                 : "=r"(r0), "=r"(r1), "=r"(r2), "=r"(r3) : "r"(addr));
}
__device__ __forceinline__ void ldmx4t(uint32_t addr, uint32_t& r0, uint32_t& r1,
                                       uint32_t& r2, uint32_t& r3) {
    asm volatile("ldmatrix.sync.aligned.m8n8.x4.trans.shared.b16 {%0,%1,%2,%3}, [%4];"
                 : "=r"(r0), "=r"(r1), "=r"(r2), "=r"(r3) : "r"(addr));
}
__device__ __forceinline__ void mma16816(float* d, const uint32_t* a,
                                         uint32_t b0, uint32_t b1) {
    asm volatile(
        "mma.sync.aligned.m16n8k16.row.col.f32.bf16.bf16.f32 "
        "{%0,%1,%2,%3}, {%4,%5,%6,%7}, {%8,%9}, {%0,%1,%2,%3};"
        : "+f"(d[0]), "+f"(d[1]), "+f"(d[2]), "+f"(d[3])
        : "r"(a[0]), "r"(a[1]), "r"(a[2]), "r"(a[3]), "r"(b0), "r"(b1));
}
__device__ __forceinline__ void cp16(uint32_t dst, const void* src) {
    asm volatile("cp.async.cg.shared.global [%0], [%1], 16;"
                 :: "r"(dst), "l"(__cvta_generic_to_global(src)));
}
#define CP_COMMIT() asm volatile("cp.async.commit_group;")
#define CP_WAIT(n)  asm volatile("cp.async.wait_group %0;" :: "n"(n))
__device__ __forceinline__ float ex2f(float x) {
    float y;
    asm("ex2.approx.f32 %0, %1;" : "=f"(y) : "f"(x));
    return y;
}

// ---------------- fp32 -> bf16 convert (weights) ----------------------------
__global__ void f2bf_kernel(const float* __restrict__ src,
                            __nv_bfloat16* __restrict__ dst, int n4)
{
    int i = blockIdx.x * 256 + threadIdx.x;
    if (i < n4) {
        float4 v = ((const float4*)src)[i];
        __nv_bfloat162 h0 = __floats2bfloat162_rn(v.x, v.y);
        __nv_bfloat162 h1 = __floats2bfloat162_rn(v.z, v.w);
        uint2 w;
        w.x = *(uint32_t*)&h0; w.y = *(uint32_t*)&h1;
        ((uint2*)dst)[i] = w;
    }
}

// ---------------- RMSNorm (fp32 in -> bf16 out) ------------------------------
__global__ void rmsnorm_kernel(const float* __restrict__ x,
                               const float* __restrict__ w)
{
    const int row = blockIdx.x;
    const int t = threadIdx.x;
    const float4 v = ((const float4*)(x + (size_t)row * DD))[t];
    float ss = v.x*v.x + v.y*v.y + v.z*v.z + v.w*v.w;
    #pragma unroll
    for (int o = 16; o; o >>= 1) ss += __shfl_xor_sync(0xffffffffu, ss, o);
    __shared__ float swarp[8];
    __shared__ float s_r;
    if ((t & 31) == 0) swarp[t >> 5] = ss;
    __syncthreads();
    if (t < 8) {
        float tot = swarp[t];
        #pragma unroll
        for (int o = 4; o; o >>= 1) tot += __shfl_xor_sync(0xffu, tot, o);
        if (t == 0) s_r = rsqrtf(tot * (1.0f / DD) + 1e-6f);
    }
    __syncthreads();
    const float r = s_r;
    const float4 wv = ((const float4*)w)[t];
    __nv_bfloat162 h0 = __floats2bfloat162_rn(v.x * r * wv.x, v.y * r * wv.y);
    __nv_bfloat162 h1 = __floats2bfloat162_rn(v.z * r * wv.z, v.w * r * wv.w);
    uint2 o2;
    o2.x = *(uint32_t*)&h0; o2.y = *(uint32_t*)&h1;
    ((uint2*)(g_xn_bf + (size_t)row * DD))[t] = o2;
}

// ============ mma.sync bf16 GEMM:  C[M,N] = A[M,K] @ B[N,K]^T  ==============
// CTA tile 256x128, 8 warps (warp tile 64x64), K-chunk 32, 3-stage cp.async.
// smem rows padded to 80B -> conflict-free ldmatrix.
#define GPAD 80                        // bytes per 32-bf16 smem row
#define GTILE_A (256 * GPAD)           // 20480 bytes (A) per stage
#define GTILE_B (128 * GPAD)           // 10240 bytes (B) per stage
#define GSTAGE (GTILE_A + GTILE_B)     // 30720
#define GSMEM (3 * GSTAGE)             // 92160 bytes

// OBF: write bf16 output.  EPI: C = res + (*rsp)*acc (fp32 out).
template<bool EPI, bool OBF>
__global__ void __launch_bounds__(256) gemm_mma(
    const __nv_bfloat16* __restrict__ A, const __nv_bfloat16* __restrict__ Bm,
    void* __restrict__ Cv, int N, int K,
    const float* __restrict__ res, const float* __restrict__ rsp)
{
    extern __shared__ char gsm[];
    const uint32_t s0 = smem_u32(gsm);
    const int tid  = threadIdx.x;
    const int lane = tid & 31, wid = tid >> 5;
    const int tM = blockIdx.y * 256, tN = blockIdx.x * 128;
    const int wm = (wid & 3) * 64, wn = (wid >> 2) * 64;

    const __nv_bfloat16* Ag = A  + (size_t)tM * K;
    const __nv_bfloat16* Bg = Bm + (size_t)tN * K;

    float acc[32][4];
    #pragma unroll
    for (int i = 0; i < 32; i++)
        #pragma unroll
        for (int j = 0; j < 4; j++) acc[i][j] = 0.f;

    // stage loader: A 256x32, B 128x32 bf16
    auto load_stage = [&](int kc, int st) {
        const uint32_t base = s0 + st * GSTAGE;
        #pragma unroll
        for (int t = 0; t < 4; t++) {
            int idx = tid + t * 256;          // 0..1023
            int row = idx >> 2, c = idx & 3;
            cp16(base + row * GPAD + c * 16,
                 Ag + (size_t)row * K + kc * 32 + c * 8);
        }
        #pragma unroll
        for (int t = 0; t < 2; t++) {
            int idx = tid + t * 256;          // 0..511
            int row = idx >> 2, c = idx & 3;
            cp16(base + GTILE_A + row * GPAD + c * 16,
                 Bg + (size_t)row * K + kc * 32 + c * 8);
        }
        CP_COMMIT();
    };

    const int NKC = K / 32;
    load_stage(0, 0);
    load_stage(1, 1);

    const uint32_t rowoff = (lane & 15) * GPAD;
    const uint32_t colhi  = (lane & 16);

    int st = 0;
    for (int kc = 0; kc < NKC; kc++) {
        CP_WAIT(1);
        __syncthreads();

        const uint32_t aT = s0 + st * GSTAGE + wm * GPAD;
        const uint32_t bT = s0 + st * GSTAGE + GTILE_A + wn * GPAD;
        #pragma unroll
        for (int s = 0; s < 2; s++) {
            const uint32_t col = s * 32 + colhi;
            uint32_t a[4][4], b[4][4];
            #pragma unroll
            for (int mi = 0; mi < 4; mi++)
                ldmx4(aT + mi * 16 * GPAD + rowoff + col,
                      a[mi][0], a[mi][1], a[mi][2], a[mi][3]);
            #pragma unroll
            for (int ni = 0; ni < 4; ni++)
                ldmx4(bT + ni * 16 * GPAD + rowoff + col,
                      b[ni][0], b[ni][1], b[ni][2], b[ni][3]);
            #pragma unroll
            for (int mi = 0; mi < 4; mi++)
                #pragma unroll
                for (int ni = 0; ni < 4; ni++) {
                    mma16816(acc[mi * 8 + ni * 2 + 0], a[mi], b[ni][0], b[ni][2]);
                    mma16816(acc[mi * 8 + ni * 2 + 1], a[mi], b[ni][1], b[ni][3]);
                }
        }

        if (kc + 2 < NKC)
            load_stage(kc + 2, (st + 2 >= 3) ? st - 1 : st + 2);
        st = (st + 1 == 3) ? 0 : st + 1;
    }

    // ---- epilogue ----
    const float s_res = EPI ? *rsp : 0.f;
    const int g = lane >> 2, q = lane & 3;
    #pragma unroll
    for (int mi = 0; mi < 4; mi++) {
        const int row0 = tM + wm + mi * 16 + g;
        #pragma unroll
        for (int nj = 0; nj < 8; nj++) {
            const int col = tN + wn + nj * 8 + q * 2;
            const float* ac = acc[mi * 8 + nj];
            #pragma unroll
            for (int h = 0; h < 2; h++) {
                const size_t o = (size_t)(row0 + h * 8) * N + col;
                if (OBF) {
                    __nv_bfloat162 hp = __floats2bfloat162_rn(ac[h * 2 + 0],
                                                              ac[h * 2 + 1]);
                    *(uint32_t*)((__nv_bfloat16*)Cv + o) = *(uint32_t*)&hp;
                } else {
                    float2 w;
                    if (EPI) {
                        float2 r2 = *(const float2*)(res + o);
                        w.x = fmaf(s_res, ac[h * 2 + 0], r2.x);
                        w.y = fmaf(s_res, ac[h * 2 + 1], r2.y);
                    } else {
                        w.x = ac[h * 2 + 0];
                        w.y = ac[h * 2 + 1];
                    }
                    *(float2*)((float*)Cv + o) = w;
                }
            }
        }
    }
}

// ---------------- RoPE + scatter qkv(bf16) -> q/k/v (bf16) [B,H,L,hd] -------
__global__ void rope_scatter_kernel()
{
    const int t  = blockIdx.x * 256 + threadIdx.x;
    const int bl = t / 1536;
    const int r  = t - bl * 1536;
    const int w  = r >> 9;          // 0=q,1=k,2=v
    const int h  = (r >> 7) & 3;
    const int dp = r & 127;
    const __nv_bfloat16* src = g_qkv_bf + (size_t)bl * 3072 + w * 1024 + h * 256 + dp;
    const float x0 = __bfloat162float(src[0]);
    const float x1 = __bfloat162float(src[128]);
    const int b = bl >> 11;
    const int l = bl & 2047;
    __nv_bfloat16* base = (w == 0) ? g_q : (w == 1) ? g_k : g_v;
    __nv_bfloat16* dst = base + ((size_t)(b * HH + h) * LL + l) * HD + dp;
    if (w < 2) {
        // 10000^(-dp/128) = 2^(-dp * log2(10000)/128)
        const float invf = exp2f((float)dp * (-13.287712379549449f / 128.0f));
        const float ang  = (float)l * invf;
        float s, c;
        sincosf(ang, &s, &c);
        dst[0]   = __float2bfloat16(x0 * c - x1 * s);
        dst[128] = __float2bfloat16(x1 * c + x0 * s);
    } else {
        dst[0]   = __float2bfloat16(x0);
        dst[128] = __float2bfloat16(x1);
    }
}

// ---------------- Flash attention v2 (register-resident softmax) ------------
// CTA = 128 q-rows; 8 warps; each warp owns 16 q-rows x ALL 64 keys x 256 hd.
#define FKSTB 528               // 264 bf16 row stride (bytes)
#define FK_OFF 67584            // Q tile bytes (128 x 264 bf16)
#define FV_OFF 135168
#define FKV_BUF 33792           // one K or V buffer (64 x 264 bf16)
#define FLASH_SMEM 202752

__global__ void __launch_bounds__(256, 1) flash_mma()
{
    extern __shared__ char fsm[];
    const uint32_t sQ = smem_u32(fsm);
    const uint32_t sK = sQ + FK_OFF, sV = sQ + FV_OFF;

    const int tid = threadIdx.x;
    const int lane = tid & 31, wid = tid >> 5;
    const int g = lane >> 2, qd = lane & 3;
    const int m0w = wid * 16;
    const int bh = blockIdx.y;
    const int q0 = blockIdx.x * 128;

    const __nv_bfloat16* Qg = g_q + ((size_t)bh * LL + q0) * HD;
    const __nv_bfloat16* Kg = g_k + (size_t)bh * LL * HD;
    const __nv_bfloat16* Vg = g_v + (size_t)bh * LL * HD;

    // load Q tile (128 x 256 bf16)
    #pragma unroll
    for (int it = 0; it < 16; it++) {
        int idx = tid + it * 256;            // 4096 16B chunks
        int row = idx >> 5, c = idx & 31;
        uint4 v = ((const uint4*)(Qg + (size_t)row * HD))[c];
        *(uint4*)(fsm + row * FKSTB + c * 16) = v;
    }

    auto load_kv = [&](int kt, int buf) {
        const __nv_bfloat16* Kt = Kg + (size_t)kt * 64 * HD;
        const __nv_bfloat16* Vt = Vg + (size_t)kt * 64 * HD;
        const uint32_t kb = sK + buf * FKV_BUF;
        const uint32_t vb = sV + buf * FKV_BUF;
        #pragma unroll
        for (int t = 0; t < 8; t++) {
            int idx = tid + t * 256;
            int row = idx >> 5, c = idx & 31;
            cp16(kb + row * FKSTB + c * 16, Kt + (size_t)row * HD + c * 8);
        }
        CP_COMMIT();
        #pragma unroll
        for (int t = 0; t < 8; t++) {
            int idx = tid + t * 256;
            int row = idx >> 5, c = idx & 31;
            cp16(vb + row * FKSTB + c * 16, Vt + (size_t)row * HD + c * 8);
        }
        CP_COMMIT();
    };

    float accO[32][4];
    #pragma unroll
    for (int nj = 0; nj < 32; nj++)
        #pragma unroll
        for (int k = 0; k < 4; k++) accO[nj][k] = 0.f;
    float rm0 = -1e30f, rm1 = -1e30f, rl0 = 0.f, rl1 = 0.f;

    const uint32_t lrow = (lane & 15), lhi = (lane & 16);
    const float SC = 0.0625f * 1.44269504f;   // 1/sqrt(256) * log2(e)

    load_kv(0, 0);

    for (int kt = 0; kt < 32; kt++) {
        const int cur = kt & 1;
        if (kt < 31) { load_kv(kt + 1, cur ^ 1); CP_WAIT(2); }
        else         { CP_WAIT(0); }
        __syncthreads();
        const uint32_t sKb = sK + cur * FKV_BUF;
        const uint32_t sVb = sV + cur * FKV_BUF;

        // ---- S = Q K^T  (warp tile 16 x 64, k = 256) ----
        float accS[8][4];
        #pragma unroll
        for (int nj = 0; nj < 8; nj++)
            #pragma unroll
            for (int k = 0; k < 4; k++) accS[nj][k] = 0.f;
        #pragma unroll
        for (int ks = 0; ks < 16; ks++) {
            const uint32_t colb = ks * 32 + lhi;
            uint32_t a[4];
            ldmx4(sQ + (m0w + lrow) * FKSTB + colb, a[0], a[1], a[2], a[3]);
            #pragma unroll
            for (int kb = 0; kb < 4; kb++) {
                uint32_t br[4];
                ldmx4(sKb + (kb * 16 + lrow) * FKSTB + colb,
                      br[0], br[1], br[2], br[3]);
                mma16816(accS[kb * 2 + 0], a, br[0], br[2]);
                mma16816(accS[kb * 2 + 1], a, br[1], br[3]);
            }
        }

        // ---- register softmax (rows g and g+8 of this warp's 16) ----
        #pragma unroll
        for (int nj = 0; nj < 8; nj++)
            #pragma unroll
            for (int k = 0; k < 4; k++) accS[nj][k] *= SC;
        float mx0 = rm0, mx1 = rm1;
        #pragma unroll
        for (int nj = 0; nj < 8; nj++) {
            mx0 = fmaxf(mx0, fmaxf(accS[nj][0], accS[nj][1]));
            mx1 = fmaxf(mx1, fmaxf(accS[nj][2], accS[nj][3]));
        }
        mx0 = fmaxf(mx0, __shfl_xor_sync(0xffffffffu, mx0, 1));
        mx0 = fmaxf(mx0, __shfl_xor_sync(0xffffffffu, mx0, 2));
        mx1 = fmaxf(mx1, __shfl_xor_sync(0xffffffffu, mx1, 1));
        mx1 = fmaxf(mx1, __shfl_xor_sync(0xffffffffu, mx1, 2));
        const float al0 = ex2f(rm0 - mx0);
        const float al1 = ex2f(rm1 - mx1);
        rm0 = mx0; rm1 = mx1;

        float sum0 = 0.f, sum1 = 0.f;
        uint32_t pa[4][4];
        #pragma unroll
        for (int nj = 0; nj < 8; nj++) {
            float p0 = ex2f(accS[nj][0] - mx0);
            float p1 = ex2f(accS[nj][1] - mx0);
            float p2 = ex2f(accS[nj][2] - mx1);
            float p3 = ex2f(accS[nj][3] - mx1);
            sum0 += p0 + p1;
            sum1 += p2 + p3;
            __nv_bfloat162 h01 = __floats2bfloat162_rn(p0, p1);
            __nv_bfloat162 h23 = __floats2bfloat162_rn(p2, p3);
            const int kk = nj >> 1, hf = nj & 1;
            pa[kk][hf * 2 + 0] = *(uint32_t*)&h01;
            pa[kk][hf * 2 + 1] = *(uint32_t*)&h23;
        }
        sum0 += __shfl_xor_sync(0xffffffffu, sum0, 1);
        sum0 += __shfl_xor_sync(0xffffffffu, sum0, 2);
        sum1 += __shfl_xor_sync(0xffffffffu, sum1, 1);
        sum1 += __shfl_xor_sync(0xffffffffu, sum1, 2);
        rl0 = rl0 * al0 + sum0;
        rl1 = rl1 * al1 + sum1;

        // ---- O = O*alpha + P V  (warp tile 16 x 256, k = 64) ----
        #pragma unroll
        for (int nj = 0; nj < 32; nj++) {
            accO[nj][0] *= al0; accO[nj][1] *= al0;
            accO[nj][2] *= al1; accO[nj][3] *= al1;
        }
        #pragma unroll
        for (int ks = 0; ks < 4; ks++) {
            const uint32_t vrow = ks * 16 + lrow;
            #pragma unroll
            for (int np = 0; np < 16; np++) {
                uint32_t vb[4];
                ldmx4t(sVb + vrow * FKSTB + np * 32 + lhi,
                       vb[0], vb[1], vb[2], vb[3]);
                mma16816(accO[np * 2 + 0], pa[ks], vb[0], vb[1]);
                mma16816(accO[np * 2 + 1], pa[ks], vb[2], vb[3]);
            }
        }
        __syncthreads();
    }

    // ---- epilogue: O /= l, write bf16 to g_ao_bf [B,L,H*hd] ----
    const int b = bh >> 2, h = bh & 3;
    const int r0 = q0 + m0w + g;
    const float li0 = 1.0f / rl0;
    const float li1 = 1.0f / rl1;
    __nv_bfloat16* d1 = g_ao_bf + ((size_t)(b * LL + r0) * DD + h * HD);
    __nv_bfloat16* d2 = d1 + 8 * DD;
    #pragma unroll
    for (int nj = 0; nj < 32; nj++) {
        const int col = nj * 8 + qd * 2;
        __nv_bfloat162 h1 = __floats2bfloat162_rn(accO[nj][0] * li0,
                                                  accO[nj][1] * li0);
        __nv_bfloat162 h2 = __floats2bfloat162_rn(accO[nj][2] * li1,
                                                  accO[nj][3] * li1);
        *(uint32_t*)(d1 + col) = *(uint32_t*)&h1;
        *(uint32_t*)(d2 + col) = *(uint32_t*)&h2;
    }
}

// ---------------- launch -----------------------------------------------------
extern "C" void kernel_launch(void* const* d_in, const int* in_sizes, int n_in,
                              void* d_out, int out_size)
{
    const float* x      = (const float*)d_in[0];
    const float* norm_w = (const float*)d_in[1];
    const float* qkv_w  = (const float*)d_in[2];
    const float* out_w  = (const float*)d_in[3];
    const float* rsp    = (const float*)d_in[4];
    float* out = (float*)d_out;

    __nv_bfloat16 *p_xn, *p_wqkv, *p_wout, *p_ao, *p_qkv;
    cudaGetSymbolAddress((void**)&p_xn,   g_xn_bf);
    cudaGetSymbolAddress((void**)&p_wqkv, g_wqkv_bf);
    cudaGetSymbolAddress((void**)&p_wout, g_wout_bf);
    cudaGetSymbolAddress((void**)&p_qkv,  g_qkv_bf);
    cudaGetSymbolAddress((void**)&p_ao,   g_ao_bf);

    cudaFuncSetAttribute(flash_mma,
                         cudaFuncAttributeMaxDynamicSharedMemorySize,
                         FLASH_SMEM);
    cudaFuncSetAttribute(gemm_mma<false, true>,
                         cudaFuncAttributeMaxDynamicSharedMemorySize, GSMEM);
    cudaFuncSetAttribute(gemm_mma<true, false>,
                         cudaFuncAttributeMaxDynamicSharedMemorySize, GSMEM);

    // 0. weights -> bf16
    f2bf_kernel<<<(3 * DD * DD / 4 + 255) / 256, 256>>>(qkv_w, p_wqkv, 3 * DD * DD / 4);
    f2bf_kernel<<<(DD * DD / 4 + 255) / 256, 256>>>(out_w, p_wout, DD * DD / 4);
    // 1. RMSNorm (bf16 out)
    rmsnorm_kernel<<<ROWS, 256>>>(x, norm_w);
    // 2. QKV projection (mma.sync bf16, bf16 out): [8192,3072] = xn @ qkv_w^T
    gemm_mma<false, true><<<dim3((3 * DD) / 128, ROWS / 256), 256, GSMEM>>>(
        p_xn, p_wqkv, p_qkv, 3 * DD, DD, nullptr, nullptr);
    // 3. RoPE + scatter to bf16 [B,H,L,hd]
    rope_scatter_kernel<<<(ROWS * 1536) / 256, 256>>>();
    // 4. attention (register-resident FA2, bf16 mma.sync)
    flash_mma<<<dim3(LL / 128, BHN), 256, FLASH_SMEM>>>();
    // 5. out projection + residual epilogue -> d_out (fp32)
    gemm_mma<true, false><<<dim3(DD / 128, ROWS / 256), 256, GSMEM>>>(
        p_ao, p_wout, out, DD, DD, x, rsp);
}

// round 17
// speedup vs baseline: 1.0176x; 1.0176x over previous
#include <cuda_runtime.h>
#include <cuda_bf16.h>
#include <math.h>
#include <stdint.h>

// Problem constants
#define BB 4
#define HH 4
#define LL 2048
#define DD 1024
#define HD 256
#define ROWS (BB*LL)     // 8192
#define BHN  (BB*HH)     // 16

// ---------------- scratch (device globals; no allocations allowed) ----------
__device__ __nv_bfloat16 g_xn_bf [(size_t)ROWS * DD];       // normalized x (bf16)
__device__ __nv_bfloat16 g_wqkv_bf[(size_t)3 * DD * DD];    // qkv_w in bf16
__device__ __nv_bfloat16 g_wout_bf[(size_t)DD * DD];        // out_w in bf16
__device__ __nv_bfloat16 g_qkv_bf[(size_t)ROWS * 3 * DD];   // qkv projection (bf16)
__device__ __nv_bfloat16 g_q  [(size_t)BHN * LL * HD];      // bf16 [BH,L,hd]
__device__ __nv_bfloat16 g_k  [(size_t)BHN * LL * HD];
__device__ __nv_bfloat16 g_v  [(size_t)BHN * LL * HD];
__device__ __nv_bfloat16 g_ao_bf[(size_t)ROWS * DD];        // attention out (bf16)

// =====================  helpers  ============================================
__device__ __forceinline__ uint32_t smem_u32(const void* p) {
    uint32_t a;
    asm("{ .reg .u64 t; cvta.to.shared.u64 t, %1; cvt.u32.u64 %0, t; }"
        : "=r"(a) : "l"(p));
    return a;
}
__device__ __forceinline__ void ldmx4(uint32_t addr, uint32_t& r0, uint32_t& r1,
                                      uint32_t& r2, uint32_t& r3) {
    asm volatile("ldmatrix.sync.aligned.m8n8.x4.shared.b16 {%0,%1,%2,%3}, [%4];"
                 : "=r"(r0), "=r"(r1), "=r"(r2), "=r"(r3) : "r"(addr));
}
__device__ __forceinline__ void ldmx4t(uint32_t addr, uint32_t& r0, uint32_t& r1,
                                       uint32_t& r2, uint32_t& r3) {
    asm volatile("ldmatrix.sync.aligned.m8n8.x4.trans.shared.b16 {%0,%1,%2,%3}, [%4];"
                 : "=r"(r0), "=r"(r1), "=r"(r2), "=r"(r3) : "r"(addr));
}
__device__ __forceinline__ void mma16816(float* d, const uint32_t* a,
                                         uint32_t b0, uint32_t b1) {
    asm volatile(
        "mma.sync.aligned.m16n8k16.row.col.f32.bf16.bf16.f32 "
        "{%0,%1,%2,%3}, {%4,%5,%6,%7}, {%8,%9}, {%0,%1,%2,%3};"
        : "+f"(d[0]), "+f"(d[1]), "+f"(d[2]), "+f"(d[3])
        : "r"(a[0]), "r"(a[1]), "r"(a[2]), "r"(a[3]), "r"(b0), "r"(b1));
}
__device__ __forceinline__ void cp16(uint32_t dst, const void* src) {
    asm volatile("cp.async.cg.shared.global [%0], [%1], 16;"
                 :: "r"(dst), "l"(__cvta_generic_to_global(src)));
}
#define CP_COMMIT() asm volatile("cp.async.commit_group;")
#define CP_WAIT(n)  asm volatile("cp.async.wait_group %0;" :: "n"(n))
__device__ __forceinline__ float ex2f(float x) {
    float y;
    asm("ex2.approx.f32 %0, %1;" : "=f"(y) : "f"(x));
    return y;
}

// ---------------- fp32 -> bf16 convert (weights) ----------------------------
__global__ void f2bf_kernel(const float* __restrict__ src,
                            __nv_bfloat16* __restrict__ dst, int n4)
{
    int i = blockIdx.x * 256 + threadIdx.x;
    if (i < n4) {
        float4 v = ((const float4*)src)[i];
        __nv_bfloat162 h0 = __floats2bfloat162_rn(v.x, v.y);
        __nv_bfloat162 h1 = __floats2bfloat162_rn(v.z, v.w);
        uint2 w;
        w.x = *(uint32_t*)&h0; w.y = *(uint32_t*)&h1;
        ((uint2*)dst)[i] = w;
    }
}

// ---------------- RMSNorm (fp32 in -> bf16 out) ------------------------------
__global__ void rmsnorm_kernel(const float* __restrict__ x,
                               const float* __restrict__ w)
{
    const int row = blockIdx.x;
    const int t = threadIdx.x;
    const float4 v = ((const float4*)(x + (size_t)row * DD))[t];
    float ss = v.x*v.x + v.y*v.y + v.z*v.z + v.w*v.w;
    #pragma unroll
    for (int o = 16; o; o >>= 1) ss += __shfl_xor_sync(0xffffffffu, ss, o);
    __shared__ float swarp[8];
    __shared__ float s_r;
    if ((t & 31) == 0) swarp[t >> 5] = ss;
    __syncthreads();
    if (t < 8) {
        float tot = swarp[t];
        #pragma unroll
        for (int o = 4; o; o >>= 1) tot += __shfl_xor_sync(0xffu, tot, o);
        if (t == 0) s_r = rsqrtf(tot * (1.0f / DD) + 1e-6f);
    }
    __syncthreads();
    const float r = s_r;
    const float4 wv = ((const float4*)w)[t];
    __nv_bfloat162 h0 = __floats2bfloat162_rn(v.x * r * wv.x, v.y * r * wv.y);
    __nv_bfloat162 h1 = __floats2bfloat162_rn(v.z * r * wv.z, v.w * r * wv.w);
    uint2 o2;
    o2.x = *(uint32_t*)&h0; o2.y = *(uint32_t*)&h1;
    ((uint2*)(g_xn_bf + (size_t)row * DD))[t] = o2;
}

// ============ mma.sync bf16 GEMM:  C[M,N] = A[M,K] @ B[N,K]^T  ==============
// CTA tile 128x128, 4 warps (warp tile 64x64), K-chunk 32, 3-stage cp.async.
// smem rows padded to 80B -> conflict-free ldmatrix.   (R15 config, proven)
#define GPAD 80                        // bytes per 32-bf16 smem row
#define GTILE (128 * GPAD)             // 10240 bytes per operand per stage
#define GSTAGE (2 * GTILE)             // A+B per stage
#define GSMEM (3 * GSTAGE)             // 61440 bytes

// OBF: write bf16 output.  EPI: C = res + (*rsp)*acc (fp32 out).
template<bool EPI, bool OBF>
__global__ void __launch_bounds__(128) gemm_mma(
    const __nv_bfloat16* __restrict__ A, const __nv_bfloat16* __restrict__ Bm,
    void* __restrict__ Cv, int N, int K,
    const float* __restrict__ res, const float* __restrict__ rsp)
{
    extern __shared__ char gsm[];
    const uint32_t s0 = smem_u32(gsm);
    const int tid  = threadIdx.x;
    const int lane = tid & 31, wid = tid >> 5;
    const int tM = blockIdx.y * 128, tN = blockIdx.x * 128;
    const int wm = (wid & 1) * 64, wn = (wid >> 1) * 64;

    const __nv_bfloat16* Ag = A  + (size_t)tM * K;
    const __nv_bfloat16* Bg = Bm + (size_t)tN * K;

    float acc[32][4];
    #pragma unroll
    for (int i = 0; i < 32; i++)
        #pragma unroll
        for (int j = 0; j < 4; j++) acc[i][j] = 0.f;

    // stage loader: 128x32 bf16 per operand (4 cp16 / thread / operand)
    auto load_stage = [&](int kc, int st) {
        const uint32_t base = s0 + st * GSTAGE;
        #pragma unroll
        for (int t = 0; t < 4; t++) {
            int idx = tid + t * 128;          // 0..511
            int row = idx >> 2, c = idx & 3;
            uint32_t off = row * GPAD + c * 16;
            cp16(base + off,         Ag + (size_t)row * K + kc * 32 + c * 8);
            cp16(base + GTILE + off, Bg + (size_t)row * K + kc * 32 + c * 8);
        }
        CP_COMMIT();
    };

    const int NKC = K / 32;
    load_stage(0, 0);
    load_stage(1, 1);

    const uint32_t rowoff = (lane & 15) * GPAD;
    const uint32_t colhi  = (lane & 16);

    int st = 0;
    for (int kc = 0; kc < NKC; kc++) {
        CP_WAIT(1);
        __syncthreads();

        const uint32_t aT = s0 + st * GSTAGE + wm * GPAD;
        const uint32_t bT = s0 + st * GSTAGE + GTILE + wn * GPAD;
        #pragma unroll
        for (int s = 0; s < 2; s++) {
            const uint32_t col = s * 32 + colhi;
            uint32_t a[4][4], b[4][4];
            #pragma unroll
            for (int mi = 0; mi < 4; mi++)
                ldmx4(aT + mi * 16 * GPAD + rowoff + col,
                      a[mi][0], a[mi][1], a[mi][2], a[mi][3]);
            #pragma unroll
            for (int ni = 0; ni < 4; ni++)
                ldmx4(bT + ni * 16 * GPAD + rowoff + col,
                      b[ni][0], b[ni][1], b[ni][2], b[ni][3]);
            #pragma unroll
            for (int mi = 0; mi < 4; mi++)
                #pragma unroll
                for (int ni = 0; ni < 4; ni++) {
                    mma16816(acc[mi * 8 + ni * 2 + 0], a[mi], b[ni][0], b[ni][2]);
                    mma16816(acc[mi * 8 + ni * 2 + 1], a[mi], b[ni][1], b[ni][3]);
                }
        }

        if (kc + 2 < NKC)
            load_stage(kc + 2, (st + 2 >= 3) ? st - 1 : st + 2);
        st = (st + 1 == 3) ? 0 : st + 1;
    }

    // ---- epilogue ----
    const float s_res = EPI ? *rsp : 0.f;
    const int g = lane >> 2, q = lane & 3;
    #pragma unroll
    for (int mi = 0; mi < 4; mi++) {
        const int row0 = tM + wm + mi * 16 + g;
        #pragma unroll
        for (int nj = 0; nj < 8; nj++) {
            const int col = tN + wn + nj * 8 + q * 2;
            const float* ac = acc[mi * 8 + nj];
            #pragma unroll
            for (int h = 0; h < 2; h++) {
                const size_t o = (size_t)(row0 + h * 8) * N + col;
                if (OBF) {
                    __nv_bfloat162 hp = __floats2bfloat162_rn(ac[h * 2 + 0],
                                                              ac[h * 2 + 1]);
                    *(uint32_t*)((__nv_bfloat16*)Cv + o) = *(uint32_t*)&hp;
                } else {
                    float2 w;
                    if (EPI) {
                        float2 r2 = *(const float2*)(res + o);
                        w.x = fmaf(s_res, ac[h * 2 + 0], r2.x);
                        w.y = fmaf(s_res, ac[h * 2 + 1], r2.y);
                    } else {
                        w.x = ac[h * 2 + 0];
                        w.y = ac[h * 2 + 1];
                    }
                    *(float2*)((float*)Cv + o) = w;
                }
            }
        }
    }
}

// ---------------- RoPE + scatter qkv(bf16) -> q/k/v (bf16) [B,H,L,hd] -------
__global__ void rope_scatter_kernel()
{
    const int t  = blockIdx.x * 256 + threadIdx.x;
    const int bl = t / 1536;
    const int r  = t - bl * 1536;
    const int w  = r >> 9;          // 0=q,1=k,2=v
    const int h  = (r >> 7) & 3;
    const int dp = r & 127;
    const __nv_bfloat16* src = g_qkv_bf + (size_t)bl * 3072 + w * 1024 + h * 256 + dp;
    const float x0 = __bfloat162float(src[0]);
    const float x1 = __bfloat162float(src[128]);
    const int b = bl >> 11;
    const int l = bl & 2047;
    __nv_bfloat16* base = (w == 0) ? g_q : (w == 1) ? g_k : g_v;
    __nv_bfloat16* dst = base + ((size_t)(b * HH + h) * LL + l) * HD + dp;
    if (w < 2) {
        // 10000^(-dp/128) = 2^(-dp * log2(10000)/128)
        const float invf = exp2f((float)dp * (-13.287712379549449f / 128.0f));
        const float ang  = (float)l * invf;
        float s, c;
        sincosf(ang, &s, &c);
        dst[0]   = __float2bfloat16(x0 * c - x1 * s);
        dst[128] = __float2bfloat16(x1 * c + x0 * s);
    } else {
        dst[0]   = __float2bfloat16(x0);
        dst[128] = __float2bfloat16(x1);
    }
}

// ---------------- Flash attention v3 (64-row CTAs, 2 CTA/SM) ----------------
// CTA = 64 q-rows, 128 threads / 4 warps; warp owns 16 q-rows x 64 keys x 256 hd.
// Single-buffered K and V (101 KB smem) -> 2 CTAs/SM; staggered prefetch:
// K(kt+1) issued after S-reads, V(kt+1) issued after PV-reads.
#define FKSTB 528               // 264 bf16 row stride (bytes)
#define F3_K  33792             // Q tile bytes (64 x 528)
#define F3_V  67584
#define FLASH_SMEM 101376

__global__ void __launch_bounds__(128, 2) flash_mma()
{
    extern __shared__ char fsm[];
    const uint32_t sQ = smem_u32(fsm);
    const uint32_t sK = sQ + F3_K, sV = sQ + F3_V;

    const int tid = threadIdx.x;
    const int lane = tid & 31, wid = tid >> 5;
    const int g = lane >> 2, qd = lane & 3;
    const int m0w = wid * 16;
    const int bh = blockIdx.y;
    const int q0 = blockIdx.x * 64;

    const __nv_bfloat16* Qg = g_q + ((size_t)bh * LL + q0) * HD;
    const __nv_bfloat16* Kg = g_k + (size_t)bh * LL * HD;
    const __nv_bfloat16* Vg = g_v + (size_t)bh * LL * HD;

    auto load_k = [&](int kt) {
        const __nv_bfloat16* Kt = Kg + (size_t)kt * 64 * HD;
        #pragma unroll
        for (int t = 0; t < 16; t++) {
            int idx = tid + t * 128;
            int row = idx >> 5, c = idx & 31;
            cp16(sK + row * FKSTB + c * 16, Kt + (size_t)row * HD + c * 8);
        }
        CP_COMMIT();
    };
    auto load_v = [&](int kt) {
        const __nv_bfloat16* Vt = Vg + (size_t)kt * 64 * HD;
        #pragma unroll
        for (int t = 0; t < 16; t++) {
            int idx = tid + t * 128;
            int row = idx >> 5, c = idx & 31;
            cp16(sV + row * FKSTB + c * 16, Vt + (size_t)row * HD + c * 8);
        }
        CP_COMMIT();
    };

    // prologue: async K0, V0, Q (one wait covers all)
    load_k(0);
    load_v(0);
    #pragma unroll
    for (int t = 0; t < 16; t++) {
        int idx = tid + t * 128;
        int row = idx >> 5, c = idx & 31;
        cp16(sQ + row * FKSTB + c * 16, Qg + (size_t)row * HD + c * 8);
    }
    CP_COMMIT();

    float accO[32][4];
    #pragma unroll
    for (int nj = 0; nj < 32; nj++)
        #pragma unroll
        for (int k = 0; k < 4; k++) accO[nj][k] = 0.f;
    float rm0 = -1e30f, rm1 = -1e30f, rl0 = 0.f, rl1 = 0.f;

    const uint32_t lrow = (lane & 15), lhi = (lane & 16);
    const float SC = 0.0625f * 1.44269504f;   // 1/sqrt(256) * log2(e)

    for (int kt = 0; kt < 32; kt++) {
        CP_WAIT(0);
        __syncthreads();

        // ---- S = Q K^T  (warp tile 16 x 64, k = 256) ----
        float accS[8][4];
        #pragma unroll
        for (int nj = 0; nj < 8; nj++)
            #pragma unroll
            for (int k = 0; k < 4; k++) accS[nj][k] = 0.f;
        #pragma unroll
        for (int ks = 0; ks < 16; ks++) {
            const uint32_t colb = ks * 32 + lhi;
            uint32_t a[4];
            ldmx4(sQ + (m0w + lrow) * FKSTB + colb, a[0], a[1], a[2], a[3]);
            #pragma unroll
            for (int kb = 0; kb < 4; kb++) {
                uint32_t br[4];
                ldmx4(sK + (kb * 16 + lrow) * FKSTB + colb,
                      br[0], br[1], br[2], br[3]);
                mma16816(accS[kb * 2 + 0], a, br[0], br[2]);
                mma16816(accS[kb * 2 + 1], a, br[1], br[3]);
            }
        }
        __syncthreads();                       // all warps done reading K
        if (kt < 31) load_k(kt + 1);           // prefetch K under softmax+PV

        // ---- register softmax (rows g and g+8 of this warp's 16) ----
        #pragma unroll
        for (int nj = 0; nj < 8; nj++)
            #pragma unroll
            for (int k = 0; k < 4; k++) accS[nj][k] *= SC;
        float mx0 = rm0, mx1 = rm1;
        #pragma unroll
        for (int nj = 0; nj < 8; nj++) {
            mx0 = fmaxf(mx0, fmaxf(accS[nj][0], accS[nj][1]));
            mx1 = fmaxf(mx1, fmaxf(accS[nj][2], accS[nj][3]));
        }
        mx0 = fmaxf(mx0, __shfl_xor_sync(0xffffffffu, mx0, 1));
        mx0 = fmaxf(mx0, __shfl_xor_sync(0xffffffffu, mx0, 2));
        mx1 = fmaxf(mx1, __shfl_xor_sync(0xffffffffu, mx1, 1));
        mx1 = fmaxf(mx1, __shfl_xor_sync(0xffffffffu, mx1, 2));
        const float al0 = ex2f(rm0 - mx0);
        const float al1 = ex2f(rm1 - mx1);
        rm0 = mx0; rm1 = mx1;

        float sum0 = 0.f, sum1 = 0.f;
        uint32_t pa[4][4];
        #pragma unroll
        for (int nj = 0; nj < 8; nj++) {
            float p0 = ex2f(accS[nj][0] - mx0);
            float p1 = ex2f(accS[nj][1] - mx0);
            float p2 = ex2f(accS[nj][2] - mx1);
            float p3 = ex2f(accS[nj][3] - mx1);
            sum0 += p0 + p1;
            sum1 += p2 + p3;
            __nv_bfloat162 h01 = __floats2bfloat162_rn(p0, p1);
            __nv_bfloat162 h23 = __floats2bfloat162_rn(p2, p3);
            const int kk = nj >> 1, hf = nj & 1;
            pa[kk][hf * 2 + 0] = *(uint32_t*)&h01;
            pa[kk][hf * 2 + 1] = *(uint32_t*)&h23;
        }
        sum0 += __shfl_xor_sync(0xffffffffu, sum0, 1);
        sum0 += __shfl_xor_sync(0xffffffffu, sum0, 2);
        sum1 += __shfl_xor_sync(0xffffffffu, sum1, 1);
        sum1 += __shfl_xor_sync(0xffffffffu, sum1, 2);
        rl0 = rl0 * al0 + sum0;
        rl1 = rl1 * al1 + sum1;

        // ---- O = O*alpha + P V  (warp tile 16 x 256, k = 64) ----
        #pragma unroll
        for (int nj = 0; nj < 32; nj++) {
            accO[nj][0] *= al0; accO[nj][1] *= al0;
            accO[nj][2] *= al1; accO[nj][3] *= al1;
        }
        #pragma unroll
        for (int ks = 0; ks < 4; ks++) {
            const uint32_t vrow = ks * 16 + lrow;
            #pragma unroll
            for (int np = 0; np < 16; np++) {
                uint32_t vb[4];
                ldmx4t(sV + vrow * FKSTB + np * 32 + lhi,
                       vb[0], vb[1], vb[2], vb[3]);
                mma16816(accO[np * 2 + 0], pa[ks], vb[0], vb[1]);
                mma16816(accO[np * 2 + 1], pa[ks], vb[2], vb[3]);
            }
        }
        __syncthreads();                       // all warps done reading V
        if (kt < 31) load_v(kt + 1);           // prefetch V
    }

    // ---- epilogue: O /= l, write bf16 to g_ao_bf [B,L,H*hd] ----
    const int b = bh >> 2, h = bh & 3;
    const int r0 = q0 + m0w + g;
    const float li0 = 1.0f / rl0;
    const float li1 = 1.0f / rl1;
    __nv_bfloat16* d1 = g_ao_bf + ((size_t)(b * LL + r0) * DD + h * HD);
    __nv_bfloat16* d2 = d1 + 8 * DD;
    #pragma unroll
    for (int nj = 0; nj < 32; nj++) {
        const int col = nj * 8 + qd * 2;
        __nv_bfloat162 h1 = __floats2bfloat162_rn(accO[nj][0] * li0,
                                                  accO[nj][1] * li0);
        __nv_bfloat162 h2 = __floats2bfloat162_rn(accO[nj][2] * li1,
                                                  accO[nj][3] * li1);
        *(uint32_t*)(d1 + col) = *(uint32_t*)&h1;
        *(uint32_t*)(d2 + col) = *(uint32_t*)&h2;
    }
}

// ---------------- launch -----------------------------------------------------
extern "C" void kernel_launch(void* const* d_in, const int* in_sizes, int n_in,
                              void* d_out, int out_size)
{
    const float* x      = (const float*)d_in[0];
    const float* norm_w = (const float*)d_in[1];
    const float* qkv_w  = (const float*)d_in[2];
    const float* out_w  = (const float*)d_in[3];
    const float* rsp    = (const float*)d_in[4];
    float* out = (float*)d_out;

    __nv_bfloat16 *p_xn, *p_wqkv, *p_wout, *p_ao, *p_qkv;
    cudaGetSymbolAddress((void**)&p_xn,   g_xn_bf);
    cudaGetSymbolAddress((void**)&p_wqkv, g_wqkv_bf);
    cudaGetSymbolAddress((void**)&p_wout, g_wout_bf);
    cudaGetSymbolAddress((void**)&p_qkv,  g_qkv_bf);
    cudaGetSymbolAddress((void**)&p_ao,   g_ao_bf);

    cudaFuncSetAttribute(flash_mma,
                         cudaFuncAttributeMaxDynamicSharedMemorySize,
                         FLASH_SMEM);
    cudaFuncSetAttribute(gemm_mma<false, true>,
                         cudaFuncAttributeMaxDynamicSharedMemorySize, GSMEM);
    cudaFuncSetAttribute(gemm_mma<true, false>,
                         cudaFuncAttributeMaxDynamicSharedMemorySize, GSMEM);

    // 0. weights -> bf16
    f2bf_kernel<<<(3 * DD * DD / 4 + 255) / 256, 256>>>(qkv_w, p_wqkv, 3 * DD * DD / 4);
    f2bf_kernel<<<(DD * DD / 4 + 255) / 256, 256>>>(out_w, p_wout, DD * DD / 4);
    // 1. RMSNorm (bf16 out)
    rmsnorm_kernel<<<ROWS, 256>>>(x, norm_w);
    // 2. QKV projection (mma.sync bf16, bf16 out): [8192,3072] = xn @ qkv_w^T
    gemm_mma<false, true><<<dim3((3 * DD) / 128, ROWS / 128), 128, GSMEM>>>(
        p_xn, p_wqkv, p_qkv, 3 * DD, DD, nullptr, nullptr);
    // 3. RoPE + scatter to bf16 [B,H,L,hd]
    rope_scatter_kernel<<<(ROWS * 1536) / 256, 256>>>();
    // 4. attention (64-row CTAs, 2 CTA/SM, bf16 mma.sync)
    flash_mma<<<dim3(LL / 64, BHN), 128, FLASH_SMEM>>>();
    // 5. out projection + residual epilogue -> d_out (fp32)
    gemm_mma<true, false><<<dim3(DD / 128, ROWS / 128), 128, GSMEM>>>(
        p_ao, p_wout, out, DD, DD, x, rsp);
}